// round 1
// baseline (speedup 1.0000x reference)
#include <cuda_runtime.h>
#include <math.h>

// Problem dims
#define SQ  512
#define DD  3072
#define DHH 256
#define EE  4
#define FF  8192
#define RR  16
#define H1N 128

// GEMM tiling
#define BM 64
#define BN 64
#define BK 16
#define LDP 68   // smem pitch (floats), 16B-aligned, conflict-spread

// ---------------- device scratch (no allocations allowed) ----------------
__device__ float g_h1x[SQ*H1N];
__device__ float g_hh[H1N];
__device__ float g_hp[EE*H1N];
__device__ float g_logits[EE*SQ];
__device__ int   g_cnt[EE];
__device__ int   g_tok[EE*SQ];
__device__ float g_wgt[EE*SQ];
__device__ int   g_slot[EE*SQ];
__device__ float g_xa[EE*SQ*32];          // per (e, listpos): 16 gate + 16 up LoRA projections
__device__ float g_had[EE*SQ*RR];         // per (e, listpos): down LoRA projection
__device__ float g_hbuf[EE*SQ*FF];        // 64 MB: silu(g)*u rows per (e, listpos)
__device__ float g_scr[2*SQ*DD];          // slot0/slot1 weighted expert outputs

// ---------------- K0: history + persona projections ----------------
__global__ void k0_hist_persona(const float* __restrict__ hist,
                                const float* __restrict__ persona,
                                const float* __restrict__ fw1h,
                                const float* __restrict__ fw1p) {
    int k = threadIdx.x;  // 128
    float acc = 0.f;
    const float4* h4 = (const float4*)hist;
    const float4* w4 = (const float4*)(fw1h + (size_t)k*DHH);
    for (int i = 0; i < DHH/4; i++) {
        float4 a = h4[i], b = w4[i];
        acc += a.x*b.x + a.y*b.y + a.z*b.z + a.w*b.w;
    }
    g_hh[k] = acc;
    for (int e = 0; e < EE; e++) {
        const float4* p4 = (const float4*)(persona + (size_t)e*DD);
        const float4* q4 = (const float4*)(fw1p + (size_t)k*DD);
        float a2 = 0.f;
        for (int i = 0; i < DD/4; i++) {
            float4 a = p4[i], b = q4[i];
            a2 += a.x*b.x + a.y*b.y + a.z*b.z + a.w*b.w;
        }
        g_hp[e*H1N + k] = a2;
    }
}

// ---------------- K1: h1x[s,k] = x[s,:] . fw1x[k,:] ----------------
__global__ void k1_h1x(const float* __restrict__ x,
                       const float* __restrict__ fw1x) {
    __shared__ float4 xs[DD/4];
    int s = blockIdx.x;
    const float4* xr = (const float4*)(x + (size_t)s*DD);
    for (int i = threadIdx.x; i < DD/4; i += blockDim.x) xs[i] = xr[i];
    __syncthreads();
    int k = threadIdx.x;  // 128
    const float4* wr = (const float4*)(fw1x + (size_t)k*DD);
    float acc = 0.f;
    #pragma unroll 4
    for (int i = 0; i < DD/4; i++) {
        float4 a = xs[i], b = wr[i];
        acc += a.x*b.x + a.y*b.y + a.z*b.z + a.w*b.w;
    }
    g_h1x[s*H1N + k] = acc;
}

// ---------------- K2: fused MLP -> relu -> LN -> gate logit ----------------
__global__ __launch_bounds__(256) void k2_logits(
        const float* __restrict__ fb1, const float* __restrict__ fw2,
        const float* __restrict__ fb2, const float* __restrict__ lng,
        const float* __restrict__ lnb, const float* __restrict__ gw,
        const float* __restrict__ gb) {
    int s = blockIdx.x, e = blockIdx.y, tid = threadIdx.x;
    __shared__ float h1r[H1N];
    __shared__ float red[256];
    if (tid < H1N) {
        float v = g_h1x[s*H1N + tid] + g_hh[tid] + fb1[tid] + g_hp[e*H1N + tid];
        h1r[tid] = fmaxf(v, 0.f);
    }
    __syncthreads();
    float f[DD/256];
    float sum = 0.f, sumsq = 0.f;
    #pragma unroll
    for (int i = 0; i < DD/256; i++) {
        int d = tid + i*256;
        const float4* wr = (const float4*)(fw2 + (size_t)d*H1N);
        float acc = fb2[d];
        #pragma unroll
        for (int k4 = 0; k4 < H1N/4; k4++) {
            float4 b  = wr[k4];
            float4 hv = *(const float4*)&h1r[k4*4];
            acc += hv.x*b.x + hv.y*b.y + hv.z*b.z + hv.w*b.w;
        }
        acc = fmaxf(acc, 0.f);
        f[i] = acc; sum += acc; sumsq += acc*acc;
    }
    red[tid] = sum; __syncthreads();
    for (int o = 128; o > 0; o >>= 1) { if (tid < o) red[tid] += red[tid+o]; __syncthreads(); }
    float mean = red[0] * (1.f/DD);
    __syncthreads();
    red[tid] = sumsq; __syncthreads();
    for (int o = 128; o > 0; o >>= 1) { if (tid < o) red[tid] += red[tid+o]; __syncthreads(); }
    float var  = red[0] * (1.f/DD) - mean*mean;
    float rstd = rsqrtf(var + 1e-5f);
    __syncthreads();
    float ls = 0.f;
    #pragma unroll
    for (int i = 0; i < DD/256; i++) {
        int d = tid + i*256;
        ls += ((f[i] - mean)*rstd*lng[d] + lnb[d]) * gw[d];
    }
    red[tid] = ls; __syncthreads();
    for (int o = 128; o > 0; o >>= 1) { if (tid < o) red[tid] += red[tid+o]; __syncthreads(); }
    if (tid == 0) g_logits[e*SQ + s] = red[0] + gb[0];
}

// ---------------- K3: softmax / top-2 / routing lists / entropy ----------------
__global__ void k3_route(float* __restrict__ d_out, int out_size) {
    int s = threadIdx.x;  // 512
    __shared__ float er[SQ];
    if (s < EE) g_cnt[s] = 0;
    __syncthreads();
    float l[EE];
    #pragma unroll
    for (int e = 0; e < EE; e++) l[e] = g_logits[e*SQ + s];
    float m = fmaxf(fmaxf(l[0], l[1]), fmaxf(l[2], l[3]));
    float p[EE]; float psum = 0.f;
    #pragma unroll
    for (int e = 0; e < EE; e++) { p[e] = expf(l[e]-m); psum += p[e]; }
    float inv = 1.f/psum;
    float ent = 0.f;
    #pragma unroll
    for (int e = 0; e < EE; e++) { p[e] *= inv; ent -= p[e]*logf(p[e] + 1e-9f); }
    int e0 = 0; float b0 = p[0];
    #pragma unroll
    for (int e = 1; e < EE; e++) if (p[e] > b0) { b0 = p[e]; e0 = e; }
    int e1 = -1; float b1 = -1.f;
    #pragma unroll
    for (int e = 0; e < EE; e++) if (e != e0 && p[e] > b1) { b1 = p[e]; e1 = e; }
    int i0 = atomicAdd(&g_cnt[e0], 1);
    g_tok[e0*SQ + i0] = s; g_wgt[e0*SQ + i0] = p[e0]; g_slot[e0*SQ + i0] = 0;
    int i1 = atomicAdd(&g_cnt[e1], 1);
    g_tok[e1*SQ + i1] = s; g_wgt[e1*SQ + i1] = p[e1]; g_slot[e1*SQ + i1] = 1;
    er[s] = ent; __syncthreads();
    for (int o = 256; o > 0; o >>= 1) { if (s < o) er[s] += er[s+o]; __syncthreads(); }
    if (s == 0 && out_size > SQ*DD) d_out[SQ*DD] = er[0] * (1.f/SQ);
}

// ---------------- E1: x LoRA projections (gate/up), per routed token ----------------
__global__ void e1_xa(const float* __restrict__ x,
                      const float* __restrict__ Ag,
                      const float* __restrict__ Au) {
    int e = blockIdx.y, i = blockIdx.x;
    if (i >= g_cnt[e]) return;
    int tok = g_tok[e*SQ + i];
    const float4* xr = (const float4*)(x + (size_t)tok*DD);
    int warp = threadIdx.x >> 5, lane = threadIdx.x & 31;
    for (int o = warp; o < 32; o += 4) {
        const float* A = (o < 16) ? Ag : Au;
        int r = o & 15;
        const float4* ar = (const float4*)(A + ((size_t)e*RR + r)*DD);
        float acc = 0.f;
        for (int qv = lane; qv < DD/4; qv += 32) {
            float4 a = xr[qv], b = ar[qv];
            acc += a.x*b.x + a.y*b.y + a.z*b.z + a.w*b.w;
        }
        #pragma unroll
        for (int off = 16; off; off >>= 1) acc += __shfl_down_sync(0xffffffffu, acc, off);
        if (lane == 0) g_xa[((size_t)e*SQ + i)*32 + o] = acc;
    }
}

// ---------------- E2: fused gate+up GEMM + LoRA + SiLU*up -> h ----------------
__global__ __launch_bounds__(256) void e2_gateup(
        const float* __restrict__ x,
        const float* __restrict__ Wg, const float* __restrict__ Wu,
        const float* __restrict__ Bg, const float* __restrict__ Bu) {
    int e = blockIdx.z;
    int n_e = g_cnt[e];
    int m0 = blockIdx.y * BM;
    if (m0 >= n_e) return;
    int n0 = blockIdx.x * BN;
    __shared__ int   toks[BM];
    __shared__ float Xs[BK][LDP], Gs[BK][LDP], Us[BK][LDP];
    __shared__ float xas[BM][32];
    __shared__ float bgs[BM][17], bus[BM][17];
    int tid = threadIdx.x;
    if (tid < BM) toks[tid] = g_tok[e*SQ + min(m0 + tid, n_e - 1)];
    __syncthreads();
    int row = tid >> 2, qv = tid & 3;
    int ty = tid >> 4, tx = tid & 15;
    const float* xp = x + (size_t)toks[row]*DD + qv*4;
    size_t wb = (size_t)e*FF*DD + (size_t)(n0+row)*DD + qv*4;
    const float* gp = Wg + wb;
    const float* up = Wu + wb;
    float accg[4][4] = {}, accu[4][4] = {};
    for (int kk = 0; kk < DD; kk += BK) {
        float4 a  = *(const float4*)(xp + kk);
        float4 bg = *(const float4*)(gp + kk);
        float4 bu = *(const float4*)(up + kk);
        __syncthreads();
        Xs[qv*4+0][row]=a.x;  Xs[qv*4+1][row]=a.y;  Xs[qv*4+2][row]=a.z;  Xs[qv*4+3][row]=a.w;
        Gs[qv*4+0][row]=bg.x; Gs[qv*4+1][row]=bg.y; Gs[qv*4+2][row]=bg.z; Gs[qv*4+3][row]=bg.w;
        Us[qv*4+0][row]=bu.x; Us[qv*4+1][row]=bu.y; Us[qv*4+2][row]=bu.z; Us[qv*4+3][row]=bu.w;
        __syncthreads();
        #pragma unroll
        for (int k = 0; k < BK; k++) {
            float4 av = *(const float4*)&Xs[k][ty*4];
            float4 gv = *(const float4*)&Gs[k][tx*4];
            float4 uv = *(const float4*)&Us[k][tx*4];
            float am[4] = {av.x, av.y, av.z, av.w};
            float gm[4] = {gv.x, gv.y, gv.z, gv.w};
            float um[4] = {uv.x, uv.y, uv.z, uv.w};
            #pragma unroll
            for (int i = 0; i < 4; i++)
                #pragma unroll
                for (int j = 0; j < 4; j++) {
                    accg[i][j] += am[i]*gm[j];
                    accu[i][j] += am[i]*um[j];
                }
        }
    }
    for (int t = tid; t < BM*32; t += 256) {
        int mi = t >> 5, r = t & 31;
        xas[mi][r] = g_xa[((size_t)e*SQ + min(m0+mi, n_e-1))*32 + r];
    }
    for (int t = tid; t < BM*RR; t += 256) {
        int fi = t >> 4, r = t & 15;
        size_t bi = ((size_t)e*FF + n0 + fi)*RR + r;
        bgs[fi][r] = Bg[bi];
        bus[fi][r] = Bu[bi];
    }
    __syncthreads();
    #pragma unroll
    for (int r = 0; r < RR; r++) {
        float ag[4], au[4], bgv[4], buv[4];
        #pragma unroll
        for (int i = 0; i < 4; i++) { ag[i] = xas[ty*4+i][r]; au[i] = xas[ty*4+i][16+r]; }
        #pragma unroll
        for (int j = 0; j < 4; j++) { bgv[j] = bgs[tx*4+j][r]; buv[j] = bus[tx*4+j][r]; }
        #pragma unroll
        for (int i = 0; i < 4; i++)
            #pragma unroll
            for (int j = 0; j < 4; j++) {
                accg[i][j] += ag[i]*bgv[j];
                accu[i][j] += au[i]*buv[j];
            }
    }
    #pragma unroll
    for (int i = 0; i < 4; i++) {
        int m = m0 + ty*4 + i;
        if (m < n_e) {
            float* hr = g_hbuf + ((size_t)e*SQ + m)*FF + n0 + tx*4;
            float4 hv;
            { float gg = accg[i][0], uu = accu[i][0]; hv.x = gg*uu/(1.f+__expf(-gg)); }
            { float gg = accg[i][1], uu = accu[i][1]; hv.y = gg*uu/(1.f+__expf(-gg)); }
            { float gg = accg[i][2], uu = accu[i][2]; hv.z = gg*uu/(1.f+__expf(-gg)); }
            { float gg = accg[i][3], uu = accu[i][3]; hv.w = gg*uu/(1.f+__expf(-gg)); }
            *(float4*)hr = hv;
        }
    }
}

// ---------------- E3: h LoRA projection (down), per routed token ----------------
__global__ void e3_ha(const float* __restrict__ Ad) {
    int e = blockIdx.y, i = blockIdx.x;
    if (i >= g_cnt[e]) return;
    const float4* hr = (const float4*)(g_hbuf + ((size_t)e*SQ + i)*FF);
    int warp = threadIdx.x >> 5, lane = threadIdx.x & 31;
    for (int r = warp; r < RR; r += 4) {
        const float4* ar = (const float4*)(Ad + ((size_t)e*RR + r)*FF);
        float acc = 0.f;
        for (int qv = lane; qv < FF/4; qv += 32) {
            float4 a = hr[qv], b = ar[qv];
            acc += a.x*b.x + a.y*b.y + a.z*b.z + a.w*b.w;
        }
        #pragma unroll
        for (int off = 16; off; off >>= 1) acc += __shfl_down_sync(0xffffffffu, acc, off);
        if (lane == 0) g_had[((size_t)e*SQ + i)*RR + r] = acc;
    }
}

// ---------------- E4: down GEMM + LoRA, weighted write to slot scratch ----------------
__global__ __launch_bounds__(256) void e4_down(const float* __restrict__ Wd,
                                               const float* __restrict__ Bd) {
    int e = blockIdx.z;
    int n_e = g_cnt[e];
    int m0 = blockIdx.y * BM;
    if (m0 >= n_e) return;
    int n0 = blockIdx.x * BN;
    __shared__ int   toks[BM];
    __shared__ float wts[BM];
    __shared__ int   slts[BM];
    __shared__ float Hs[BK][LDP], Ws[BK][LDP];
    __shared__ float hds[BM][17], bds[BM][17];
    int tid = threadIdx.x;
    if (tid < BM) {
        int li = e*SQ + min(m0 + tid, n_e - 1);
        toks[tid] = g_tok[li]; wts[tid] = g_wgt[li]; slts[tid] = g_slot[li];
    }
    __syncthreads();
    int row = tid >> 2, qv = tid & 3, ty = tid >> 4, tx = tid & 15;
    const float* hp_ = g_hbuf + ((size_t)e*SQ + min(m0+row, n_e-1))*FF + qv*4;
    const float* wp_ = Wd + ((size_t)e*DD + n0 + row)*FF + qv*4;
    float acc[4][4] = {};
    for (int kk = 0; kk < FF; kk += BK) {
        float4 a = *(const float4*)(hp_ + kk);
        float4 b = *(const float4*)(wp_ + kk);
        __syncthreads();
        Hs[qv*4+0][row]=a.x; Hs[qv*4+1][row]=a.y; Hs[qv*4+2][row]=a.z; Hs[qv*4+3][row]=a.w;
        Ws[qv*4+0][row]=b.x; Ws[qv*4+1][row]=b.y; Ws[qv*4+2][row]=b.z; Ws[qv*4+3][row]=b.w;
        __syncthreads();
        #pragma unroll
        for (int k = 0; k < BK; k++) {
            float4 av = *(const float4*)&Hs[k][ty*4];
            float4 bv = *(const float4*)&Ws[k][tx*4];
            float am[4] = {av.x, av.y, av.z, av.w};
            float bm[4] = {bv.x, bv.y, bv.z, bv.w};
            #pragma unroll
            for (int i = 0; i < 4; i++)
                #pragma unroll
                for (int j = 0; j < 4; j++)
                    acc[i][j] += am[i]*bm[j];
        }
    }
    for (int t = tid; t < BM*RR; t += 256) {
        int mi = t >> 4, r = t & 15;
        hds[mi][r] = g_had[((size_t)e*SQ + min(m0+mi, n_e-1))*RR + r];
        bds[mi][r] = Bd[((size_t)e*DD + n0 + mi)*RR + r];
    }
    __syncthreads();
    #pragma unroll
    for (int r = 0; r < RR; r++) {
        float hv[4], bv[4];
        #pragma unroll
        for (int i = 0; i < 4; i++) hv[i] = hds[ty*4+i][r];
        #pragma unroll
        for (int j = 0; j < 4; j++) bv[j] = bds[tx*4+j][r];
        #pragma unroll
        for (int i = 0; i < 4; i++)
            #pragma unroll
            for (int j = 0; j < 4; j++)
                acc[i][j] += hv[i]*bv[j];
    }
    #pragma unroll
    for (int i = 0; i < 4; i++) {
        int m = m0 + ty*4 + i;
        if (m < n_e) {
            int li = ty*4 + i;
            int tok = toks[li]; float w = wts[li]; int sl = slts[li];
            float* orow = g_scr + ((size_t)sl*SQ + tok)*DD + n0 + tx*4;
            *(float4*)orow = make_float4(acc[i][0]*w, acc[i][1]*w, acc[i][2]*w, acc[i][3]*w);
        }
    }
}

// ---------------- E5: deterministic slot combine ----------------
__global__ void e5_combine(float* __restrict__ out) {
    int i = blockIdx.x*blockDim.x + threadIdx.x;  // float4 index
    const float4* a = (const float4*)g_scr;
    const float4* b = (const float4*)(g_scr + (size_t)SQ*DD);
    float4 va = a[i], vb = b[i];
    ((float4*)out)[i] = make_float4(va.x+vb.x, va.y+vb.y, va.z+vb.z, va.w+vb.w);
}

// ---------------- launch ----------------
extern "C" void kernel_launch(void* const* d_in, const int* in_sizes, int n_in,
                              void* d_out, int out_size) {
    const float* x       = (const float*)d_in[0];
    const float* hist    = (const float*)d_in[1];
    const float* persona = (const float*)d_in[2];
    const float* fw1x    = (const float*)d_in[3];
    const float* fw1h    = (const float*)d_in[4];
    const float* fw1p    = (const float*)d_in[5];
    const float* fb1     = (const float*)d_in[6];
    const float* fw2     = (const float*)d_in[7];
    const float* fb2     = (const float*)d_in[8];
    const float* lng     = (const float*)d_in[9];
    const float* lnb     = (const float*)d_in[10];
    const float* gw      = (const float*)d_in[11];
    const float* gb      = (const float*)d_in[12];
    const float* Wg      = (const float*)d_in[13];
    const float* Wu      = (const float*)d_in[14];
    const float* Wd      = (const float*)d_in[15];
    const float* Ag      = (const float*)d_in[16];
    const float* Bg      = (const float*)d_in[17];
    const float* Au      = (const float*)d_in[18];
    const float* Bu      = (const float*)d_in[19];
    const float* Ad      = (const float*)d_in[20];
    const float* Bd      = (const float*)d_in[21];
    float* out = (float*)d_out;

    k0_hist_persona<<<1, 128>>>(hist, persona, fw1h, fw1p);
    k1_h1x<<<SQ, 128>>>(x, fw1x);
    dim3 g2(SQ, EE);
    k2_logits<<<g2, 256>>>(fb1, fw2, fb2, lng, lnb, gw, gb);
    k3_route<<<1, SQ>>>(out, out_size);
    dim3 ge1(SQ, EE);
    e1_xa<<<ge1, 128>>>(x, Ag, Au);
    dim3 ge2(FF/BN, SQ/BM, EE);
    e2_gateup<<<ge2, 256>>>(x, Wg, Wu, Bg, Bu);
    dim3 ge3(SQ, EE);
    e3_ha<<<ge3, 128>>>(Ad);
    dim3 ge4(DD/BN, SQ/BM, EE);
    e4_down<<<ge4, 256>>>(Wd, Bd);
    e5_combine<<<(SQ*DD)/(256*4), 256>>>(out);
}

// round 7
// speedup vs baseline: 2.1303x; 2.1303x over previous
#include <cuda_runtime.h>
#include <cstdint>
#include <math.h>

// Problem dims
#define SQ  512
#define DD  3072
#define DHH 256
#define EE  4
#define FF  8192
#define RR  16
#define H1N 128

// SIMT GEMM tiling (gating)
#define BK 16
#define LDP 68

// mma tiling
#define P2 20         // smem pitch in floats for K=16 chunks (+4 pad)

// ================= device scratch =================
__device__ float g_h1x[SQ*H1N];
__device__ float g_hh[H1N];
__device__ float g_hp[EE*H1N];
__device__ float g_cc[2];                 // c3 = sum(lng*gw), c2 = sum(lnb*gw)
__device__ float g_logits[EE*SQ];
__device__ int   g_cnt[EE];
__device__ int   g_tok[EE*SQ];
__device__ float g_wgt[EE*SQ];
__device__ int   g_slot[EE*SQ];
__device__ float g_xa[EE*SQ*32];          // 16 gate + 16 up LoRA x-projections
__device__ float g_had[EE*SQ*RR];         // down LoRA h-projection
__device__ float g_hbuf[(size_t)EE*SQ*FF];// silu(g)*u rows per (e, listpos)
__device__ float g_scr[2*SQ*DD];          // slot0/slot1 weighted expert outputs

// ================= mma helpers =================
__device__ __forceinline__ uint32_t f2tf32(float f) {
    uint32_t u;
    asm("cvt.rna.tf32.f32 %0, %1;" : "=r"(u) : "f"(f));
    return u;
}
__device__ __forceinline__ void sts_tf32x4(uint32_t* dst, float4 v) {
    uint4 o;
    o.x = f2tf32(v.x); o.y = f2tf32(v.y); o.z = f2tf32(v.z); o.w = f2tf32(v.w);
    *(uint4*)dst = o;
}
__device__ __forceinline__ void mma8(float* c, const uint32_t* a, uint32_t b0, uint32_t b1) {
    asm volatile(
        "mma.sync.aligned.m16n8k8.row.col.f32.tf32.tf32.f32 "
        "{%0,%1,%2,%3}, {%4,%5,%6,%7}, {%8,%9}, {%0,%1,%2,%3};"
        : "+f"(c[0]), "+f"(c[1]), "+f"(c[2]), "+f"(c[3])
        : "r"(a[0]), "r"(a[1]), "r"(a[2]), "r"(a[3]), "r"(b0), "r"(b1));
}

// ================= K0: history/persona projections + LN-fold constants =================
__global__ void k0_hist_persona(const float* __restrict__ hist,
                                const float* __restrict__ persona,
                                const float* __restrict__ fw1h,
                                const float* __restrict__ fw1p,
                                const float* __restrict__ lng,
                                const float* __restrict__ lnb,
                                const float* __restrict__ gw) {
    __shared__ float r3[128], r2[128];
    int k = threadIdx.x;  // 128
    float acc = 0.f;
    const float4* h4 = (const float4*)hist;
    const float4* w4 = (const float4*)(fw1h + (size_t)k*DHH);
    for (int i = 0; i < DHH/4; i++) {
        float4 a = h4[i], b = w4[i];
        acc += a.x*b.x + a.y*b.y + a.z*b.z + a.w*b.w;
    }
    g_hh[k] = acc;
    for (int e = 0; e < EE; e++) {
        const float4* p4 = (const float4*)(persona + (size_t)e*DD);
        const float4* q4 = (const float4*)(fw1p + (size_t)k*DD);
        float a2 = 0.f;
        for (int i = 0; i < DD/4; i++) {
            float4 a = p4[i], b = q4[i];
            a2 += a.x*b.x + a.y*b.y + a.z*b.z + a.w*b.w;
        }
        g_hp[e*H1N + k] = a2;
    }
    float c3 = 0.f, c2 = 0.f;
    for (int d = k; d < DD; d += 128) { c3 += lng[d]*gw[d]; c2 += lnb[d]*gw[d]; }
    r3[k] = c3; r2[k] = c2; __syncthreads();
    for (int o = 64; o > 0; o >>= 1) { if (k < o) { r3[k] += r3[k+o]; r2[k] += r2[k+o]; } __syncthreads(); }
    if (k == 0) { g_cc[0] = r3[0]; g_cc[1] = r2[0]; }
}

// ================= K1: tiled SGEMM  h1x[s,k] = x . fw1x^T =================
__global__ __launch_bounds__(256) void k1t(const float* __restrict__ x,
                                           const float* __restrict__ fw1x) {
    int n0 = blockIdx.x * 64, m0 = blockIdx.y * 64;
    __shared__ float Xs[BK][LDP], Ws[BK][LDP];
    int tid = threadIdx.x;
    int row = tid >> 2, qv = tid & 3, ty = tid >> 4, tx = tid & 15;
    const float* xp = x + (size_t)(m0+row)*DD + qv*4;
    const float* wp = fw1x + (size_t)(n0+row)*DD + qv*4;
    float acc[4][4] = {};
    for (int kk = 0; kk < DD; kk += BK) {
        float4 a = *(const float4*)(xp + kk);
        float4 b = *(const float4*)(wp + kk);
        __syncthreads();
        Xs[qv*4+0][row]=a.x; Xs[qv*4+1][row]=a.y; Xs[qv*4+2][row]=a.z; Xs[qv*4+3][row]=a.w;
        Ws[qv*4+0][row]=b.x; Ws[qv*4+1][row]=b.y; Ws[qv*4+2][row]=b.z; Ws[qv*4+3][row]=b.w;
        __syncthreads();
        #pragma unroll
        for (int k = 0; k < BK; k++) {
            float4 av = *(const float4*)&Xs[k][ty*4];
            float4 bv = *(const float4*)&Ws[k][tx*4];
            float am[4] = {av.x, av.y, av.z, av.w};
            float bm[4] = {bv.x, bv.y, bv.z, bv.w};
            #pragma unroll
            for (int i = 0; i < 4; i++)
                #pragma unroll
                for (int j = 0; j < 4; j++)
                    acc[i][j] += am[i]*bm[j];
        }
    }
    #pragma unroll
    for (int i = 0; i < 4; i++) {
        int m = m0 + ty*4 + i;
        *(float4*)(g_h1x + (size_t)m*H1N + n0 + tx*4) =
            make_float4(acc[i][0], acc[i][1], acc[i][2], acc[i][3]);
    }
}

// ================= K2: batched fused MLP -> LN-folded logit =================
__global__ __launch_bounds__(256) void k2b(const float* __restrict__ fb1,
                                           const float* __restrict__ fw2,
                                           const float* __restrict__ fb2,
                                           const float* __restrict__ lng,
                                           const float* __restrict__ gw,
                                           const float* __restrict__ gb) {
    int e = blockIdx.y;
    int s0 = blockIdx.x * 8;
    int tid = threadIdx.x;
    __shared__ float h1r[8][H1N];
    __shared__ float red[8][8][3];
    for (int i = tid; i < 8*H1N; i += 256) {
        int t = i >> 7, k = i & 127;
        float v = g_h1x[(size_t)(s0+t)*H1N + k] + g_hh[k] + fb1[k] + g_hp[e*H1N + k];
        h1r[t][k] = fmaxf(v, 0.f);
    }
    __syncthreads();
    float s1[8] = {}, s2[8] = {}, s3[8] = {};
    for (int i = 0; i < DD/256; i++) {
        int d = tid + i*256;
        const float4* wr = (const float4*)(fw2 + (size_t)d*H1N);
        float acc[8] = {};
        #pragma unroll 8
        for (int k4 = 0; k4 < H1N/4; k4++) {
            float4 b = wr[k4];
            #pragma unroll
            for (int t = 0; t < 8; t++) {
                float4 a = *(const float4*)&h1r[t][k4*4];
                acc[t] += a.x*b.x + a.y*b.y + a.z*b.z + a.w*b.w;
            }
        }
        float bias = fb2[d], c1 = lng[d]*gw[d];
        #pragma unroll
        for (int t = 0; t < 8; t++) {
            float f = fmaxf(acc[t] + bias, 0.f);
            s1[t] += f; s2[t] += f*f; s3[t] += f*c1;
        }
    }
    #pragma unroll
    for (int t = 0; t < 8; t++) {
        #pragma unroll
        for (int o = 16; o; o >>= 1) {
            s1[t] += __shfl_down_sync(~0u, s1[t], o);
            s2[t] += __shfl_down_sync(~0u, s2[t], o);
            s3[t] += __shfl_down_sync(~0u, s3[t], o);
        }
    }
    int wid = tid >> 5, lane = tid & 31;
    if (lane == 0) {
        #pragma unroll
        for (int t = 0; t < 8; t++) {
            red[wid][t][0] = s1[t]; red[wid][t][1] = s2[t]; red[wid][t][2] = s3[t];
        }
    }
    __syncthreads();
    if (tid < 8) {
        float a = 0.f, b = 0.f, c = 0.f;
        #pragma unroll
        for (int w = 0; w < 8; w++) { a += red[w][tid][0]; b += red[w][tid][1]; c += red[w][tid][2]; }
        float mean = a * (1.f/DD);
        float var  = b * (1.f/DD) - mean*mean;
        float rstd = rsqrtf(var + 1e-5f);
        g_logits[e*SQ + s0 + tid] = rstd*(c - mean*g_cc[0]) + g_cc[1] + gb[0];
    }
}

// ================= K3: softmax / top-2 / routing / entropy =================
__global__ void k3_route(float* __restrict__ d_out, int out_size) {
    int s = threadIdx.x;  // 512
    __shared__ float er[SQ];
    if (s < EE) g_cnt[s] = 0;
    __syncthreads();
    float l[EE];
    #pragma unroll
    for (int e = 0; e < EE; e++) l[e] = g_logits[e*SQ + s];
    float m = fmaxf(fmaxf(l[0], l[1]), fmaxf(l[2], l[3]));
    float p[EE]; float psum = 0.f;
    #pragma unroll
    for (int e = 0; e < EE; e++) { p[e] = expf(l[e]-m); psum += p[e]; }
    float inv = 1.f/psum;
    float ent = 0.f;
    #pragma unroll
    for (int e = 0; e < EE; e++) { p[e] *= inv; ent -= p[e]*logf(p[e] + 1e-9f); }
    int e0 = 0; float b0 = p[0];
    #pragma unroll
    for (int e = 1; e < EE; e++) if (p[e] > b0) { b0 = p[e]; e0 = e; }
    int e1 = -1; float b1 = -1.f;
    #pragma unroll
    for (int e = 0; e < EE; e++) if (e != e0 && p[e] > b1) { b1 = p[e]; e1 = e; }
    int i0 = atomicAdd(&g_cnt[e0], 1);
    g_tok[e0*SQ + i0] = s; g_wgt[e0*SQ + i0] = p[e0]; g_slot[e0*SQ + i0] = 0;
    int i1 = atomicAdd(&g_cnt[e1], 1);
    g_tok[e1*SQ + i1] = s; g_wgt[e1*SQ + i1] = p[e1]; g_slot[e1*SQ + i1] = 1;
    er[s] = ent; __syncthreads();
    for (int o = 256; o > 0; o >>= 1) { if (s < o) er[s] += er[s+o]; __syncthreads(); }
    if (s == 0 && out_size > SQ*DD) d_out[SQ*DD] = er[0] * (1.f/SQ);
}

// ================= E1: x LoRA projections (gate/up) =================
__global__ void e1_xa(const float* __restrict__ x,
                      const float* __restrict__ Ag,
                      const float* __restrict__ Au) {
    int e = blockIdx.y, i = blockIdx.x;
    if (i >= g_cnt[e]) return;
    int tok = g_tok[e*SQ + i];
    const float4* xr = (const float4*)(x + (size_t)tok*DD);
    int warp = threadIdx.x >> 5, lane = threadIdx.x & 31;
    for (int o = warp; o < 32; o += 4) {
        const float* A = (o < 16) ? Ag : Au;
        int r = o & 15;
        const float4* ar = (const float4*)(A + ((size_t)e*RR + r)*DD);
        float acc = 0.f;
        for (int qv = lane; qv < DD/4; qv += 32) {
            float4 a = xr[qv], b = ar[qv];
            acc += a.x*b.x + a.y*b.y + a.z*b.z + a.w*b.w;
        }
        #pragma unroll
        for (int off = 16; off; off >>= 1) acc += __shfl_down_sync(0xffffffffu, acc, off);
        if (lane == 0) g_xa[((size_t)e*SQ + i)*32 + o] = acc;
    }
}

// ================= E2: mma.sync tf32 gate+up GEMM + LoRA-as-K + SiLU =================
// Block tile 128(m) x 64(n), 8 warps (2m x 4n), warp tile 64x16.
// K chunks of 16: DD/16 = 192 main + chunk 192 (gate LoRA) + chunk 193 (up LoRA).
__global__ __launch_bounds__(256) void e2_mma(const float* __restrict__ x,
                                              const float* __restrict__ Wg,
                                              const float* __restrict__ Wu,
                                              const float* __restrict__ Bg,
                                              const float* __restrict__ Bu) {
    int e = blockIdx.z;
    int n_e = g_cnt[e];
    int m0 = blockIdx.x * 128;
    if (m0 >= n_e) return;
    int n0 = blockIdx.y * 64;
    __shared__ uint32_t As[2][128*P2];
    __shared__ uint32_t Gs[2][64*P2];
    __shared__ uint32_t Us[2][64*P2];
    __shared__ int toks[128];
    int tid = threadIdx.x, lane = tid & 31, wid = tid >> 5;
    int wm = wid >> 2, wn = wid & 3;
    if (tid < 128) toks[tid] = g_tok[e*SQ + min(m0 + tid, n_e - 1)];
    __syncthreads();

    const int NCH = DD/16;           // 192
    const int TCH = NCH + 2;         // + gate-LoRA + up-LoRA

    // ldg slot assignments
    int ar0 = tid >> 2, akq = tid & 3;      // A rows tid>>2 and tid>>2+64
    int gr = tid >> 2, gkq = tid & 3;       // G/U: 64 rows x 4 quads

    float4 ra0, ra1, rg, ru;
    auto load_chunk = [&](int kc) {
        if (kc < NCH) {
            int kb = kc*16;
            ra0 = *(const float4*)(x + (size_t)toks[ar0]*DD    + kb + akq*4);
            ra1 = *(const float4*)(x + (size_t)toks[ar0+64]*DD + kb + akq*4);
            rg  = *(const float4*)(Wg + ((size_t)e*FF + n0 + gr)*DD + kb + gkq*4);
            ru  = *(const float4*)(Wu + ((size_t)e*FF + n0 + gr)*DD + kb + gkq*4);
        } else {
            int off = (kc == NCH) ? 0 : 16;  // gate cols 0-15, up cols 16-31
            int li0 = e*SQ + min(m0 + ar0, n_e - 1);
            int li1 = e*SQ + min(m0 + ar0 + 64, n_e - 1);
            ra0 = *(const float4*)(g_xa + (size_t)li0*32 + off + akq*4);
            ra1 = *(const float4*)(g_xa + (size_t)li1*32 + off + akq*4);
            if (kc == NCH) rg = *(const float4*)(Bg + ((size_t)e*FF + n0 + gr)*RR + gkq*4);
            else           ru = *(const float4*)(Bu + ((size_t)e*FF + n0 + gr)*RR + gkq*4);
        }
    };
    auto store_chunk = [&](int s, int kc) {
        sts_tf32x4(&As[s][ ar0*P2      + akq*4], ra0);
        sts_tf32x4(&As[s][(ar0+64)*P2  + akq*4], ra1);
        if (kc != NCH+1) sts_tf32x4(&Gs[s][gr*P2 + gkq*4], rg);
        if (kc != NCH)   sts_tf32x4(&Us[s][gr*P2 + gkq*4], ru);
    };

    float accg[4][2][4] = {}, accu[4][2][4] = {};

    load_chunk(0);
    store_chunk(0, 0);
    __syncthreads();

    for (int kc = 0; kc < TCH; kc++) {
        int s = kc & 1;
        if (kc + 1 < TCH) load_chunk(kc + 1);
        bool dog = (kc != NCH+1), dou = (kc != NCH);
        #pragma unroll
        for (int ks = 0; ks < 2; ks++) {
            int kb = ks*8 + (lane & 3);
            uint32_t a[4][4];
            #pragma unroll
            for (int mt = 0; mt < 4; mt++) {
                const uint32_t* ap = &As[s][(wm*64 + mt*16 + (lane >> 2))*P2 + kb];
                a[mt][0] = ap[0];     a[mt][2] = ap[4];
                a[mt][1] = ap[8*P2];  a[mt][3] = ap[8*P2 + 4];
            }
            #pragma unroll
            for (int nt = 0; nt < 2; nt++) {
                const uint32_t* gp = &Gs[s][(wn*16 + nt*8 + (lane >> 2))*P2 + kb];
                const uint32_t* up = &Us[s][(wn*16 + nt*8 + (lane >> 2))*P2 + kb];
                uint32_t g0 = gp[0], g1 = gp[4];
                uint32_t u0 = up[0], u1 = up[4];
                #pragma unroll
                for (int mt = 0; mt < 4; mt++) {
                    if (dog) mma8(accg[mt][nt], a[mt], g0, g1);
                    if (dou) mma8(accu[mt][nt], a[mt], u0, u1);
                }
            }
        }
        if (kc + 1 < TCH) {
            __syncthreads();
            store_chunk((kc + 1) & 1, kc + 1);
            __syncthreads();
        }
    }

    // epilogue: silu(g)*u -> g_hbuf
    #pragma unroll
    for (int mt = 0; mt < 4; mt++) {
        #pragma unroll
        for (int half = 0; half < 2; half++) {
            int mrow = wm*64 + mt*16 + (lane >> 2) + half*8;
            int m = m0 + mrow;
            if (m < n_e) {
                float* hr = g_hbuf + ((size_t)e*SQ + m)*FF + n0;
                #pragma unroll
                for (int nt = 0; nt < 2; nt++) {
                    int col = wn*16 + nt*8 + 2*(lane & 3);
                    float gg0 = accg[mt][nt][half*2+0], uu0 = accu[mt][nt][half*2+0];
                    float gg1 = accg[mt][nt][half*2+1], uu1 = accu[mt][nt][half*2+1];
                    float2 hv;
                    hv.x = gg0*uu0/(1.f + __expf(-gg0));
                    hv.y = gg1*uu1/(1.f + __expf(-gg1));
                    *(float2*)(hr + col) = hv;
                }
            }
        }
    }
}

// ================= E3: h LoRA projection (down) =================
__global__ void e3_ha(const float* __restrict__ Ad) {
    int e = blockIdx.y, i = blockIdx.x;
    if (i >= g_cnt[e]) return;
    const float4* hr = (const float4*)(g_hbuf + ((size_t)e*SQ + i)*FF);
    int warp = threadIdx.x >> 5, lane = threadIdx.x & 31;
    for (int r = warp; r < RR; r += 4) {
        const float4* ar = (const float4*)(Ad + ((size_t)e*RR + r)*FF);
        float acc = 0.f;
        for (int qv = lane; qv < FF/4; qv += 32) {
            float4 a = hr[qv], b = ar[qv];
            acc += a.x*b.x + a.y*b.y + a.z*b.z + a.w*b.w;
        }
        #pragma unroll
        for (int off = 16; off; off >>= 1) acc += __shfl_down_sync(0xffffffffu, acc, off);
        if (lane == 0) g_had[((size_t)e*SQ + i)*RR + r] = acc;
    }
}

// ================= E4: mma.sync tf32 down GEMM + LoRA-as-K + weighted slot write =================
// Block tile 128(m) x 64(n of D), K chunks of 16: FF/16 = 512 main + 1 LoRA.
__global__ __launch_bounds__(256) void e4_mma(const float* __restrict__ Wd,
                                              const float* __restrict__ Bd) {
    int e = blockIdx.z;
    int n_e = g_cnt[e];
    int m0 = blockIdx.x * 128;
    if (m0 >= n_e) return;
    int n0 = blockIdx.y * 64;
    __shared__ uint32_t As[2][128*P2];
    __shared__ uint32_t Ws[2][64*P2];
    __shared__ int   toks[128];
    __shared__ float wts[128];
    __shared__ int   slts[128];
    int tid = threadIdx.x, lane = tid & 31, wid = tid >> 5;
    int wm = wid >> 2, wn = wid & 3;
    if (tid < 128) {
        int li = e*SQ + min(m0 + tid, n_e - 1);
        toks[tid] = g_tok[li]; wts[tid] = g_wgt[li]; slts[tid] = g_slot[li];
    }
    __syncthreads();

    const int NCH = FF/16;           // 512
    const int TCH = NCH + 1;

    int ar0 = tid >> 2, akq = tid & 3;
    int gr = tid >> 2, gkq = tid & 3;
    int li0 = e*SQ + min(m0 + ar0, n_e - 1);
    int li1 = e*SQ + min(m0 + ar0 + 64, n_e - 1);

    float4 ra0, ra1, rw;
    auto load_chunk = [&](int kc) {
        if (kc < NCH) {
            int kb = kc*16;
            ra0 = *(const float4*)(g_hbuf + (size_t)li0*FF + kb + akq*4);
            ra1 = *(const float4*)(g_hbuf + (size_t)li1*FF + kb + akq*4);
            rw  = *(const float4*)(Wd + ((size_t)e*DD + n0 + gr)*FF + kb + gkq*4);
        } else {
            ra0 = *(const float4*)(g_had + (size_t)li0*RR + akq*4);
            ra1 = *(const float4*)(g_had + (size_t)li1*RR + akq*4);
            rw  = *(const float4*)(Bd + ((size_t)e*DD + n0 + gr)*RR + gkq*4);
        }
    };
    auto store_chunk = [&](int s) {
        sts_tf32x4(&As[s][ ar0*P2     + akq*4], ra0);
        sts_tf32x4(&As[s][(ar0+64)*P2 + akq*4], ra1);
        sts_tf32x4(&Ws[s][gr*P2 + gkq*4], rw);
    };

    float acc[4][2][4] = {};

    load_chunk(0);
    store_chunk(0);
    __syncthreads();

    for (int kc = 0; kc < TCH; kc++) {
        int s = kc & 1;
        if (kc + 1 < TCH) load_chunk(kc + 1);
        #pragma unroll
        for (int ks = 0; ks < 2; ks++) {
            int kb = ks*8 + (lane & 3);
            uint32_t a[4][4];
            #pragma unroll
            for (int mt = 0; mt < 4; mt++) {
                const uint32_t* ap = &As[s][(wm*64 + mt*16 + (lane >> 2))*P2 + kb];
                a[mt][0] = ap[0];     a[mt][2] = ap[4];
                a[mt][1] = ap[8*P2];  a[mt][3] = ap[8*P2 + 4];
            }
            #pragma unroll
            for (int nt = 0; nt < 2; nt++) {
                const uint32_t* wp = &Ws[s][(wn*16 + nt*8 + (lane >> 2))*P2 + kb];
                uint32_t w0 = wp[0], w1 = wp[4];
                #pragma unroll
                for (int mt = 0; mt < 4; mt++)
                    mma8(acc[mt][nt], a[mt], w0, w1);
            }
        }
        if (kc + 1 < TCH) {
            __syncthreads();
            store_chunk((kc + 1) & 1);
            __syncthreads();
        }
    }

    // epilogue: weighted write to slot scratch
    #pragma unroll
    for (int mt = 0; mt < 4; mt++) {
        #pragma unroll
        for (int half = 0; half < 2; half++) {
            int mrow = wm*64 + mt*16 + (lane >> 2) + half*8;
            int m = m0 + mrow;
            if (m < n_e) {
                int tok = toks[mrow]; float w = wts[mrow]; int sl = slts[mrow];
                float* orow = g_scr + ((size_t)sl*SQ + tok)*DD + n0;
                #pragma unroll
                for (int nt = 0; nt < 2; nt++) {
                    int col = wn*16 + nt*8 + 2*(lane & 3);
                    float2 v;
                    v.x = acc[mt][nt][half*2+0] * w;
                    v.y = acc[mt][nt][half*2+1] * w;
                    *(float2*)(orow + col) = v;
                }
            }
        }
    }
}

// ================= E5: slot combine =================
__global__ void e5_combine(float* __restrict__ out) {
    int i = blockIdx.x*blockDim.x + threadIdx.x;
    const float4* a = (const float4*)g_scr;
    const float4* b = (const float4*)(g_scr + (size_t)SQ*DD);
    float4 va = a[i], vb = b[i];
    ((float4*)out)[i] = make_float4(va.x+vb.x, va.y+vb.y, va.z+vb.z, va.w+vb.w);
}

// ================= launch =================
extern "C" void kernel_launch(void* const* d_in, const int* in_sizes, int n_in,
                              void* d_out, int out_size) {
    const float* x       = (const float*)d_in[0];
    const float* hist    = (const float*)d_in[1];
    const float* persona = (const float*)d_in[2];
    const float* fw1x    = (const float*)d_in[3];
    const float* fw1h    = (const float*)d_in[4];
    const float* fw1p    = (const float*)d_in[5];
    const float* fb1     = (const float*)d_in[6];
    const float* fw2     = (const float*)d_in[7];
    const float* fb2     = (const float*)d_in[8];
    const float* lng     = (const float*)d_in[9];
    const float* lnb     = (const float*)d_in[10];
    const float* gw      = (const float*)d_in[11];
    const float* gb      = (const float*)d_in[12];
    const float* Wg      = (const float*)d_in[13];
    const float* Wu      = (const float*)d_in[14];
    const float* Wd      = (const float*)d_in[15];
    const float* Ag      = (const float*)d_in[16];
    const float* Bg      = (const float*)d_in[17];
    const float* Au      = (const float*)d_in[18];
    const float* Bu      = (const float*)d_in[19];
    const float* Ad      = (const float*)d_in[20];
    const float* Bd      = (const float*)d_in[21];
    float* out = (float*)d_out;

    k0_hist_persona<<<1, 128>>>(hist, persona, fw1h, fw1p, lng, lnb, gw);
    k1t<<<dim3(2, 8), 256>>>(x, fw1x);
    k2b<<<dim3(SQ/8, EE), 256>>>(fb1, fw2, fb2, lng, gw, gb);
    k3_route<<<1, SQ>>>(out, out_size);
    e1_xa<<<dim3(SQ, EE), 128>>>(x, Ag, Au);
    e2_mma<<<dim3(4, FF/64, EE), 256>>>(x, Wg, Wu, Bg, Bu);
    e3_ha<<<dim3(SQ, EE), 128>>>(Ad);
    e4_mma<<<dim3(4, DD/64, EE), 256>>>(Wd, Bd);
    e5_combine<<<(SQ*DD)/(256*4), 256>>>(out);
}